// round 4
// baseline (speedup 1.0000x reference)
#include <cuda_runtime.h>

#define BB 4
#define HH 128
#define WW 128
#define HW (HH*WW)

typedef unsigned long long ull;

// ---------------- scratch (device globals; no runtime allocation) ----------------
__device__ float g_flow_up[BB*2*HW];
__device__ float g_f2w[BB*128*HW];
__device__ float g_corr[BB*49*HW];
__device__ float g_h1[BB*128*HW];
__device__ float g_h2[BB*64*HW];
__device__ float g_h3[BB*32*HW];

// ---------------- packed f32x2 helpers ----------------
__device__ __forceinline__ ull ffma2(ull a, ull b, ull c) {
    ull d;
    asm("fma.rn.f32x2 %0, %1, %2, %3;" : "=l"(d) : "l"(a), "l"(b), "l"(c));
    return d;
}
__device__ __forceinline__ ull pack2(float lo, float hi) {
    ull r;
    asm("mov.b64 %0, {%1, %2};" : "=l"(r) : "f"(lo), "f"(hi));
    return r;
}
__device__ __forceinline__ float2 unpack2(ull v) {
    float2 r;
    asm("mov.b64 {%0, %1}, %2;" : "=f"(r.x), "=f"(r.y) : "l"(v));
    return r;
}

// ---------------- 1) grouped ConvTranspose2d(2,2,k=4,s=2,p=1,groups=2) ----------------
__global__ void k_upsample(const float* __restrict__ flow, const float* __restrict__ up_w,
                           float* __restrict__ out) {
    int idx = blockIdx.x * blockDim.x + threadIdx.x;
    if (idx >= BB*2*HW) return;
    int x = idx & 127;
    int y = (idx >> 7) & 127;
    int g = (idx >> 14) & 1;
    int b = idx >> 15;
    const float* fin = flow + (b*2 + g) * 64 * 64;
    const float* wg  = up_w + g * 16;
    float acc = 0.f;
    #pragma unroll
    for (int ky = 0; ky < 4; ky++) {
        int t = y + 1 - ky;
        if (t & 1) continue;
        int i = t >> 1;
        if ((unsigned)i >= 64u) continue;
        #pragma unroll
        for (int kx = 0; kx < 4; kx++) {
            int s = x + 1 - kx;
            if (s & 1) continue;
            int j = s >> 1;
            if ((unsigned)j >= 64u) continue;
            acc += fin[i*64 + j] * wg[ky*4 + kx];
        }
    }
    out[idx] = acc;
}

// ---------------- 2) warp feature2 (bilinear, reflect border, align_corners) -------------
__device__ __forceinline__ float reflectf(float v, float n) {
    float t = fmodf(fabsf(v), 2.0f * n);
    return n - fabsf(t - n);
}

__global__ void k_warp(const float* __restrict__ f2, const float* __restrict__ fu,
                       float* __restrict__ f2w) {
    int x = threadIdx.x;
    int y = blockIdx.x;
    int b = blockIdx.y;
    int c0 = blockIdx.z * 32;

    const float* fub = fu + (size_t)b*2*HW;
    float u0 = fub[y*WW + x];
    float u1 = fub[HW + y*WW + x];

    float fx = reflectf((float)x + 0.05f*u1, 127.f);
    float fy = reflectf((float)y + 0.05f*u0, 127.f);

    float x0f = floorf(fx), y0f = floorf(fy);
    float wx = fx - x0f, wy = fy - y0f;
    int x0 = min(max((int)x0f, 0), 127);
    int x1 = min(x0 + 1, 127);
    int y0 = min(max((int)y0f, 0), 127);
    int y1 = min(y0 + 1, 127);
    float w00 = (1.f-wx)*(1.f-wy), w01 = wx*(1.f-wy);
    float w10 = (1.f-wx)*wy,       w11 = wx*wy;

    int o00 = y0*WW + x0, o01 = y0*WW + x1, o10 = y1*WW + x0, o11 = y1*WW + x1;
    const float* fb = f2  + (size_t)b*128*HW;
    float*       ob = f2w + (size_t)b*128*HW;
    int po = y*WW + x;
    #pragma unroll 4
    for (int c = c0; c < c0 + 32; c++) {
        const float* fc = fb + (size_t)c*HW;
        ob[(size_t)c*HW + po] = w00*fc[o00] + w01*fc[o01] + w10*fc[o10] + w11*fc[o11];
    }
}

// ---------------- 3) cost volume, split by dy range ----------------
// Block (16,16)=256, tile 32x16 px (2 px/thread). acc: NDY*7 packed pairs.
template<int DY0, int NDY>
__global__ void __launch_bounds__(256, 2) k_corr(const float* __restrict__ f1,
                                                 const float* __restrict__ f2w,
                                                 float* __restrict__ corr) {
    constexpr int CH = 8;
    constexpr int NROW = NDY + 15;     // rows of halo tile needed
    constexpr int NCOL = 40;           // 38 used, padded
    constexpr int FILL = NROW * 38;
    constexpr int NSLOT = (FILL + 255) / 256;

    __shared__ __align__(16) float s2[CH][NROW][NCOL];

    int tx = threadIdx.x, ty = threadIdx.y;
    int tid = ty*16 + tx;
    int bx = blockIdx.x*32, by = blockIdx.y*16, b = blockIdx.z;
    int x = bx + 2*tx, y = by + ty;

    int soff[NSLOT], goff[NSLOT];
    bool inr[NSLOT], val[NSLOT];
    #pragma unroll
    for (int s = 0; s < NSLOT; s++) {
        int i = tid + s*256;
        int r = i / 38, c = i - r*38;
        int gy = by - 3 + DY0 + r, gx = bx - 3 + c;
        inr[s] = (i < FILL);
        val[s] = inr[s] && (unsigned)gy < (unsigned)HH && (unsigned)gx < (unsigned)WW;
        soff[s] = r*NCOL + c;
        goff[s] = val[s] ? gy*WW + gx : 0;
    }

    ull acc[NDY*7];
    #pragma unroll
    for (int d = 0; d < NDY*7; d++) acc[d] = 0ull;

    const float* f1p = f1 + (size_t)b*128*HW + y*WW + x;
    const float* f2b = f2w + (size_t)b*128*HW;

    #pragma unroll 1
    for (int c0 = 0; c0 < 128; c0 += CH) {
        __syncthreads();
        #pragma unroll 1
        for (int ci = 0; ci < CH; ci++) {
            const float* cp = f2b + (size_t)(c0 + ci)*HW;
            float* sp = &s2[ci][0][0];
            #pragma unroll
            for (int s = 0; s < NSLOT; s++)
                if (inr[s]) sp[soff[s]] = val[s] ? __ldg(cp + goff[s]) : 0.f;
        }
        __syncthreads();
        #pragma unroll 1
        for (int ci = 0; ci < CH; ci++) {
            ull a = *(const ull*)(f1p + (size_t)(c0 + ci)*HW);
            #pragma unroll
            for (int dy = 0; dy < NDY; dy++) {
                const ull* row = (const ull*)&s2[ci][ty + dy][0];
                ull L0 = row[tx], L1 = row[tx+1], L2 = row[tx+2], L3 = row[tx+3];
                float2 b0 = unpack2(L0), b1 = unpack2(L1), b2 = unpack2(L2), b3 = unpack2(L3);
                ull T1 = pack2(b0.y, b1.x);
                ull T3 = pack2(b1.y, b2.x);
                ull T5 = pack2(b2.y, b3.x);
                acc[dy*7+0] = ffma2(a, L0, acc[dy*7+0]);
                acc[dy*7+1] = ffma2(a, T1, acc[dy*7+1]);
                acc[dy*7+2] = ffma2(a, L1, acc[dy*7+2]);
                acc[dy*7+3] = ffma2(a, T3, acc[dy*7+3]);
                acc[dy*7+4] = ffma2(a, L2, acc[dy*7+4]);
                acc[dy*7+5] = ffma2(a, T5, acc[dy*7+5]);
                acc[dy*7+6] = ffma2(a, L3, acc[dy*7+6]);
            }
        }
    }

    float* cb = corr + (size_t)b*49*HW + (size_t)DY0*7*HW + y*WW + x;
    #pragma unroll
    for (int d = 0; d < NDY*7; d++) {
        float2 v = unpack2(acc[d]);
        v.x *= (1.f/128.f); v.y *= (1.f/128.f);
        v.x = (v.x >= 0.f) ? v.x : 0.01f*v.x;
        v.y = (v.y >= 0.f) ? v.y : 0.01f*v.y;
        *(float2*)(cb + (size_t)d*HW) = v;
    }
}

// ---------------- 4) direct 3x3 conv: 4 px/thread, KOC out-ch, CH-channel staging --------
template<int CIN, int COUT, int KOC, int CH>
__global__ void __launch_bounds__(256, 3) k_conv(
    const float* __restrict__ in, const float* __restrict__ w,
    const float* __restrict__ bias, float* __restrict__ out,
    float slope, const float* __restrict__ addsrc)
{
    static_assert(CIN % CH == 0, "");
    constexpr int TROW = 18, TCOL = 68;
    constexpr int TFILL = 18*66;
    constexpr int WCNT = CH*KOC*9;
    constexpr int WSLOT = (WCNT + 255)/256;

    __shared__ __align__(16) float s_in[CH][TROW][TCOL];
    __shared__ __align__(16) ull s_w[WCNT];

    int tx = threadIdx.x, ty = threadIdx.y;
    int tid = ty*16 + tx;
    int bx = blockIdx.x*64, by = blockIdx.y*16;
    int ocg = blockIdx.z % (COUT/KOC);
    int b   = blockIdx.z / (COUT/KOC);
    int oc0 = ocg * KOC;

    int soff[5], goff[5];
    bool inr[5], val[5];
    #pragma unroll
    for (int s = 0; s < 5; s++) {
        int i = tid + s*256;
        int r = i / 66, c = i - r*66;
        int gy = by - 1 + r, gx = bx - 1 + c;
        inr[s] = (i < TFILL);
        val[s] = inr[s] && (unsigned)gy < (unsigned)HH && (unsigned)gx < (unsigned)WW;
        soff[s] = r*TCOL + c;
        goff[s] = val[s] ? gy*WW + gx : 0;
    }
    int wA[WSLOT];
    bool winr[WSLOT];
    #pragma unroll
    for (int s = 0; s < WSLOT; s++) {
        int i = tid + s*256;
        winr[s] = (i < WCNT);
        int ci = i / (KOC*9), rem = i % (KOC*9);
        int o = rem / 9, k = rem % 9;
        wA[s] = (o*CIN + ci)*9 + k;
    }

    const float* inb = in + (size_t)b*CIN*HW;
    float* sbase = &s_in[0][0][0];

    ull accA[KOC], accB[KOC];
    #pragma unroll
    for (int o = 0; o < KOC; o++) { accA[o] = 0ull; accB[o] = 0ull; }

    int wbase = oc0*CIN*9;

    #pragma unroll 1
    for (int c0 = 0; c0 < CIN; c0 += CH) {
        __syncthreads();
        #pragma unroll 1
        for (int ci = 0; ci < CH; ci++) {
            const float* cp = inb + (size_t)(c0 + ci)*HW;
            float* sp = sbase + ci*(TROW*TCOL);
            #pragma unroll
            for (int s = 0; s < 5; s++)
                if (inr[s]) sp[soff[s]] = val[s] ? __ldg(cp + goff[s]) : 0.f;
        }
        #pragma unroll
        for (int s = 0; s < WSLOT; s++) {
            if (winr[s]) {
                float wv = __ldg(w + wbase + c0*9 + wA[s]);
                s_w[tid + s*256] = pack2(wv, wv);
            }
        }
        __syncthreads();

        #pragma unroll 1
        for (int ci = 0; ci < CH; ci++) {
            const ull* wp = s_w + ci*(KOC*9);
            const float* tb = sbase + ci*(TROW*TCOL) + ty*TCOL;
            #pragma unroll
            for (int ky = 0; ky < 3; ky++) {
                const ull* row = (const ull*)(tb + ky*TCOL);
                ull L0 = row[2*tx], L1 = row[2*tx+1], L2 = row[2*tx+2];
                float2 a0 = unpack2(L0), a1 = unpack2(L1), a2 = unpack2(L2);
                ull T1 = pack2(a0.y, a1.x);
                ull T3 = pack2(a1.y, a2.x);
                #pragma unroll
                for (int o = 0; o < KOC; o++) {
                    ull w0 = wp[o*9 + ky*3 + 0];
                    ull w1 = wp[o*9 + ky*3 + 1];
                    ull w2 = wp[o*9 + ky*3 + 2];
                    accA[o] = ffma2(L0, w0, accA[o]);
                    accA[o] = ffma2(T1, w1, accA[o]);
                    accA[o] = ffma2(L1, w2, accA[o]);
                    accB[o] = ffma2(L1, w0, accB[o]);
                    accB[o] = ffma2(T3, w1, accB[o]);
                    accB[o] = ffma2(L2, w2, accB[o]);
                }
            }
        }
    }

    int y = by + ty;
    int x = bx + 4*tx;
    #pragma unroll
    for (int o = 0; o < KOC; o++) {
        float2 vA = unpack2(accA[o]);
        float2 vB = unpack2(accB[o]);
        float bv = bias[oc0 + o];
        vA.x += bv; vA.y += bv; vB.x += bv; vB.y += bv;
        vA.x = (vA.x >= 0.f) ? vA.x : slope*vA.x;
        vA.y = (vA.y >= 0.f) ? vA.y : slope*vA.y;
        vB.x = (vB.x >= 0.f) ? vB.x : slope*vB.x;
        vB.y = (vB.y >= 0.f) ? vB.y : slope*vB.y;
        size_t off = ((size_t)(b*COUT + oc0 + o))*HW + y*WW + x;
        if (addsrc) {
            float2 r0 = *(const float2*)(addsrc + off);
            float2 r1 = *(const float2*)(addsrc + off + 2);
            vA.x += r0.x; vA.y += r0.y; vB.x += r1.x; vB.y += r1.y;
        }
        *(float2*)(out + off)     = vA;
        *(float2*)(out + off + 2) = vB;
    }
}

// ---------------- launch ----------------
extern "C" void kernel_launch(void* const* d_in, const int* in_sizes, int n_in,
                              void* d_out, int out_size) {
    const float* feature1 = (const float*)d_in[0];
    const float* feature2 = (const float*)d_in[1];
    const float* flow     = (const float*)d_in[2];
    const float* up_w     = (const float*)d_in[3];
    const float* w1 = (const float*)d_in[4];  const float* b1 = (const float*)d_in[5];
    const float* w2 = (const float*)d_in[6];  const float* b2 = (const float*)d_in[7];
    const float* w3 = (const float*)d_in[8];  const float* b3 = (const float*)d_in[9];
    const float* w4 = (const float*)d_in[10]; const float* b4 = (const float*)d_in[11];
    float* out = (float*)d_out;

    float *p_flow_up, *p_f2w, *p_corr, *p_h1, *p_h2, *p_h3;
    cudaGetSymbolAddress((void**)&p_flow_up, g_flow_up);
    cudaGetSymbolAddress((void**)&p_f2w,     g_f2w);
    cudaGetSymbolAddress((void**)&p_corr,    g_corr);
    cudaGetSymbolAddress((void**)&p_h1,      g_h1);
    cudaGetSymbolAddress((void**)&p_h2,      g_h2);
    cudaGetSymbolAddress((void**)&p_h3,      g_h3);

    k_upsample<<<(BB*2*HW + 255)/256, 256>>>(flow, up_w, p_flow_up);
    k_warp<<<dim3(HH, BB, 4), 128>>>(feature2, p_flow_up, p_f2w);
    k_corr<0, 4><<<dim3(4, 8, BB), dim3(16, 16)>>>(feature1, p_f2w, p_corr);
    k_corr<4, 3><<<dim3(4, 8, BB), dim3(16, 16)>>>(feature1, p_f2w, p_corr);
    k_conv<49, 128, 4, 7><<<dim3(2, 8, BB*32), dim3(16, 16)>>>(p_corr, w1, b1, p_h1, 0.1f, nullptr);
    k_conv<128, 64, 4, 8><<<dim3(2, 8, BB*16), dim3(16, 16)>>>(p_h1,  w2, b2, p_h2, 0.1f, nullptr);
    k_conv<64, 32, 4, 8><<<dim3(2, 8, BB*8),  dim3(16, 16)>>>(p_h2,  w3, b3, p_h3, 0.1f, nullptr);
    k_conv<32, 2, 2, 8><<<dim3(2, 8, BB),     dim3(16, 16)>>>(p_h3,  w4, b4, out, 1.0f, p_flow_up);
}

// round 5
// speedup vs baseline: 1.2849x; 1.2849x over previous
#include <cuda_runtime.h>
#include <cstdint>

#define BB 4
#define HH 128
#define WW 128
#define HW (HH*WW)

typedef unsigned long long ull;

// ---------------- scratch ----------------
__device__ float g_flow_up[BB*2*HW];
__device__ float g_f2w[BB*128*HW];
__device__ float g_corr[BB*49*HW];
__device__ float g_h1[BB*128*HW];
__device__ float g_h2[BB*64*HW];
__device__ float g_h3[BB*32*HW];

// ---------------- helpers ----------------
__device__ __forceinline__ ull ffma2(ull a, ull b, ull c) {
    ull d;
    asm("fma.rn.f32x2 %0, %1, %2, %3;" : "=l"(d) : "l"(a), "l"(b), "l"(c));
    return d;
}
__device__ __forceinline__ ull pack2(float lo, float hi) {
    ull r;
    asm("mov.b64 %0, {%1, %2};" : "=l"(r) : "f"(lo), "f"(hi));
    return r;
}
__device__ __forceinline__ float2 unpack2(ull v) {
    float2 r;
    asm("mov.b64 {%0, %1}, %2;" : "=f"(r.x), "=f"(r.y) : "l"(v));
    return r;
}
__device__ __forceinline__ void cpasync4(uint32_t saddr, const float* g, bool v) {
    int sz = v ? 4 : 0;
    asm volatile("cp.async.ca.shared.global [%0], [%1], 4, %2;"
                 :: "r"(saddr), "l"(g), "r"(sz));
}
__device__ __forceinline__ void cpasync_commit_wait() {
    asm volatile("cp.async.commit_group;");
    asm volatile("cp.async.wait_group 0;");
}
__device__ __forceinline__ uint32_t sptr(const void* p) {
    return (uint32_t)__cvta_generic_to_shared(p);
}

// ---------------- 1) grouped ConvTranspose2d ----------------
__global__ void k_upsample(const float* __restrict__ flow, const float* __restrict__ up_w,
                           float* __restrict__ out) {
    int idx = blockIdx.x * blockDim.x + threadIdx.x;
    if (idx >= BB*2*HW) return;
    int x = idx & 127;
    int y = (idx >> 7) & 127;
    int g = (idx >> 14) & 1;
    int b = idx >> 15;
    const float* fin = flow + (b*2 + g) * 64 * 64;
    const float* wg  = up_w + g * 16;
    float acc = 0.f;
    #pragma unroll
    for (int ky = 0; ky < 4; ky++) {
        int t = y + 1 - ky;
        if (t & 1) continue;
        int i = t >> 1;
        if ((unsigned)i >= 64u) continue;
        #pragma unroll
        for (int kx = 0; kx < 4; kx++) {
            int s = x + 1 - kx;
            if (s & 1) continue;
            int j = s >> 1;
            if ((unsigned)j >= 64u) continue;
            acc += fin[i*64 + j] * wg[ky*4 + kx];
        }
    }
    out[idx] = acc;
}

// ---------------- 2) warp feature2 ----------------
__device__ __forceinline__ float reflectf(float v, float n) {
    float t = fmodf(fabsf(v), 2.0f * n);
    return n - fabsf(t - n);
}

__global__ void k_warp(const float* __restrict__ f2, const float* __restrict__ fu,
                       float* __restrict__ f2w) {
    int x = threadIdx.x;
    int y = blockIdx.x;
    int b = blockIdx.y;
    int c0 = blockIdx.z * 32;

    const float* fub = fu + (size_t)b*2*HW;
    float u0 = fub[y*WW + x];
    float u1 = fub[HW + y*WW + x];

    float fx = reflectf((float)x + 0.05f*u1, 127.f);
    float fy = reflectf((float)y + 0.05f*u0, 127.f);

    float x0f = floorf(fx), y0f = floorf(fy);
    float wx = fx - x0f, wy = fy - y0f;
    int x0 = min(max((int)x0f, 0), 127);
    int x1 = min(x0 + 1, 127);
    int y0 = min(max((int)y0f, 0), 127);
    int y1 = min(y0 + 1, 127);
    float w00 = (1.f-wx)*(1.f-wy), w01 = wx*(1.f-wy);
    float w10 = (1.f-wx)*wy,       w11 = wx*wy;

    int o00 = y0*WW + x0, o01 = y0*WW + x1, o10 = y1*WW + x0, o11 = y1*WW + x1;
    const float* fb = f2  + (size_t)b*128*HW;
    float*       ob = f2w + (size_t)b*128*HW;
    int po = y*WW + x;
    #pragma unroll 4
    for (int c = c0; c < c0 + 32; c++) {
        const float* fc = fb + (size_t)c*HW;
        ob[(size_t)c*HW + po] = w00*fc[o00] + w01*fc[o01] + w10*fc[o10] + w11*fc[o11];
    }
}

// ---------------- 3) cost volume: dy-parallel, 7 dx per block ----------------
// grid (4,4, B*7): z = b*7 + dy. block 128 = (tx 0..3)x(ty 0..31).
// tile 32x32 px; thread: 8 px (4 pairs) x 7 dx accumulators.
__global__ void __launch_bounds__(128, 4) k_corr7(const float* __restrict__ f1,
                                                  const float* __restrict__ f2w,
                                                  float* __restrict__ corr) {
    constexpr int CH = 8;
    constexpr int NCOL = 42;    // 38 used, even pad (8B-aligned rows)
    __shared__ float s2[CH][32][NCOL];

    int tid = threadIdx.x;
    int tx = tid & 3;
    int ty = tid >> 2;
    int bx = blockIdx.x * 32, by = blockIdx.y * 32;
    int dy = blockIdx.z % 7;
    int b  = blockIdx.z / 7;
    int x0 = bx + 8*tx;
    int y  = by + ty;

    // fill mapping: row fr (0..31), col group cg (0..3) -> cols cg+4k
    int fr = tid & 31, cg = tid >> 5;
    int gyf = by + dy - 3 + fr;
    bool gyok = (unsigned)gyf < 128u;

    ull acc[4][7];
    #pragma unroll
    for (int m = 0; m < 4; m++)
        #pragma unroll
        for (int t = 0; t < 7; t++) acc[m][t] = 0ull;

    const float* f2b = f2w + (size_t)b*128*HW;
    const float4* f1p = (const float4*)(f1 + (size_t)b*128*HW + y*WW + x0);

    #pragma unroll 1
    for (int c0 = 0; c0 < 128; c0 += CH) {
        __syncthreads();
        #pragma unroll 1
        for (int ci = 0; ci < CH; ci++) {
            const float* cp = f2b + (size_t)(c0+ci)*HW + gyf*WW;
            #pragma unroll
            for (int k = 0; k < 10; k++) {
                int c = cg + 4*k;
                if (c < 38) {
                    int gx = bx - 3 + c;
                    bool v = gyok && (unsigned)gx < 128u;
                    cpasync4(sptr(&s2[ci][fr][c]), cp + gx, v);
                }
            }
        }
        cpasync_commit_wait();
        __syncthreads();

        #pragma unroll 1
        for (int ci = 0; ci < CH; ci++) {
            const float4* p = f1p + (size_t)(c0+ci)*(HW/4);
            float4 fa = __ldg(p), fb4 = __ldg(p+1);
            ull F[4];
            F[0] = pack2(fa.x, fa.y);  F[1] = pack2(fa.z, fa.w);
            F[2] = pack2(fb4.x, fb4.y); F[3] = pack2(fb4.z, fb4.w);

            const ull* rowp = (const ull*)&s2[ci][ty][0];
            ull V[7];
            #pragma unroll
            for (int k = 0; k < 7; k++) V[k] = rowp[4*tx + k];
            ull T[6];
            #pragma unroll
            for (int q = 0; q < 6; q++) {
                float2 a = unpack2(V[q]), bb = unpack2(V[q+1]);
                T[q] = pack2(a.y, bb.x);
            }
            #pragma unroll
            for (int m = 0; m < 4; m++) {
                #pragma unroll
                for (int t = 0; t < 7; t++) {
                    int f = 2*m + t;
                    ull op = (f & 1) ? T[(f-1)>>1] : V[f>>1];
                    acc[m][t] = ffma2(F[m], op, acc[m][t]);
                }
            }
        }
    }

    float* cb = corr + ((size_t)b*49 + dy*7)*HW + y*WW + x0;
    #pragma unroll
    for (int t = 0; t < 7; t++) {
        #pragma unroll
        for (int m = 0; m < 4; m++) {
            float2 v = unpack2(acc[m][t]);
            v.x *= (1.f/128.f); v.y *= (1.f/128.f);
            v.x = (v.x >= 0.f) ? v.x : 0.01f*v.x;
            v.y = (v.y >= 0.f) ? v.y : 0.01f*v.y;
            *(float2*)(cb + (size_t)t*HW + 2*m) = v;
        }
    }
}

// ---------------- 4) 3x3 conv: crossbar-budget design ----------------
// block 256 linear: tx = tid&63 (pair col x=2tx), ry = tid>>6 (8-row band).
// tile 128x32. KOC=2, weights register-hoisted per ci. Dynamic smem.
template<int CIN, int COUT, int CH>
__global__ void __launch_bounds__(256, 2) k_conv2(
    const float* __restrict__ in, const float* __restrict__ w,
    const float* __restrict__ bias, float* __restrict__ out, float slope)
{
    constexpr int KOC = 2;
    constexpr int TCOL = 132;   // cols 0..129 used (gx -1..128), 8B-aligned stride
    extern __shared__ char dyn[];
    float* s_in = (float*)dyn;                                  // [CH][34][TCOL]
    ull*   s_w  = (ull*)(dyn + (size_t)CH*34*TCOL*sizeof(float)); // [CH*KOC*9]

    int tid = threadIdx.x;
    int tx = tid & 63;
    int ry = tid >> 6;
    int by = blockIdx.y * 32;
    int ocg = blockIdx.z % (COUT/KOC);
    int b   = blockIdx.z / (COUT/KOC);
    int oc0 = ocg * KOC;

    // fill mapping: col fcx (gx 0..127), base row fr0 (0..1), rows fr0+2k
    int fcx = tid & 127;
    int fr0 = tid >> 7;
    // weight mapping (chunk-invariant part)
    int wci = tid / 18, wrem = tid % 18;
    int wo = wrem / 9, wk = wrem % 9;
    int widx = (wo*CIN + wci)*9 + wk;   // valid when tid < CH*18

    // pre-zero permanent halo columns (gx=-1 -> col0, gx=128 -> col129)
    for (int i = tid; i < CH*34*2; i += 256) {
        int ci = i / 68, rem = i % 68, r = rem >> 1, side = rem & 1;
        s_in[(size_t)ci*34*TCOL + r*TCOL + (side ? 129 : 0)] = 0.f;
    }

    const float* inb = in + (size_t)b*CIN*HW;
    const float* wbase = w + (size_t)oc0*CIN*9;

    ull acc[KOC][8];
    #pragma unroll
    for (int o = 0; o < KOC; o++)
        #pragma unroll
        for (int r = 0; r < 8; r++) acc[o][r] = 0ull;

    #pragma unroll 1
    for (int c0 = 0; c0 < CIN; c0 += CH) {
        int chEff = (CIN - c0 < CH) ? (CIN - c0) : CH;
        __syncthreads();
        #pragma unroll 1
        for (int ci = 0; ci < chEff; ci++) {
            const float* cp = inb + (size_t)(c0+ci)*HW + fcx;
            float* sb = s_in + (size_t)ci*34*TCOL + (fcx + 1);
            #pragma unroll
            for (int k = 0; k < 17; k++) {
                int r = fr0 + 2*k;            // 0..33
                int gy = by - 1 + r;
                bool v = (unsigned)gy < 128u;
                cpasync4(sptr(sb + r*TCOL), cp + gy*WW, v);
            }
        }
        if (tid < chEff*18) {
            float wv = __ldg(wbase + c0*9 + widx);
            s_w[tid] = pack2(wv, wv);
        }
        cpasync_commit_wait();
        __syncthreads();

        #pragma unroll 1
        for (int ci = 0; ci < chEff; ci++) {
            ull wv[KOC][9];
            #pragma unroll
            for (int o = 0; o < KOC; o++)
                #pragma unroll
                for (int k = 0; k < 9; k++)
                    wv[o][k] = s_w[ci*18 + o*9 + k];

            const float* tb = s_in + (size_t)ci*34*TCOL + (size_t)(8*ry)*TCOL;
            #pragma unroll
            for (int rin = 0; rin < 10; rin++) {
                const ull* rowp = (const ull*)(tb + rin*TCOL);
                ull Ua = rowp[tx], Ub = rowp[tx+1];
                float2 ua = unpack2(Ua), ub = unpack2(Ub);
                ull T = pack2(ua.y, ub.x);
                #pragma unroll
                for (int ky = 0; ky < 3; ky++) {
                    int rr = rin - ky;
                    if (rr < 0 || rr > 7) continue;
                    #pragma unroll
                    for (int o = 0; o < KOC; o++) {
                        acc[o][rr] = ffma2(Ua, wv[o][ky*3+0], acc[o][rr]);
                        acc[o][rr] = ffma2(T,  wv[o][ky*3+1], acc[o][rr]);
                        acc[o][rr] = ffma2(Ub, wv[o][ky*3+2], acc[o][rr]);
                    }
                }
            }
        }
    }

    #pragma unroll
    for (int o = 0; o < KOC; o++) {
        float bv = bias[oc0 + o];
        float* ob = out + ((size_t)(b*COUT + oc0 + o))*HW + (size_t)(by + 8*ry)*WW + 2*tx;
        #pragma unroll
        for (int rr = 0; rr < 8; rr++) {
            float2 v = unpack2(acc[o][rr]);
            v.x += bv; v.y += bv;
            v.x = (v.x >= 0.f) ? v.x : slope*v.x;
            v.y = (v.y >= 0.f) ? v.y : slope*v.y;
            *(float2*)(ob + (size_t)rr*WW) = v;
        }
    }
}

// ---------------- 5) conv4 (tiny): proven direct template ----------------
__global__ void __launch_bounds__(256, 3) k_conv4(
    const float* __restrict__ in, const float* __restrict__ w,
    const float* __restrict__ bias, float* __restrict__ out,
    const float* __restrict__ addsrc)
{
    constexpr int CIN = 32, COUT = 2, KOC = 2, CH = 8;
    constexpr int TROW = 18, TCOL = 68;
    constexpr int TFILL = 18*66;
    constexpr int WCNT = CH*KOC*9;

    __shared__ __align__(16) float s_in[CH][TROW][TCOL];
    __shared__ __align__(16) ull s_w[WCNT];

    int tx = threadIdx.x, ty = threadIdx.y;
    int tid = ty*16 + tx;
    int bx = blockIdx.x*64, by = blockIdx.y*16;
    int b = blockIdx.z;
    int oc0 = 0;

    int soff[5], goff[5];
    bool inr[5], val[5];
    #pragma unroll
    for (int s = 0; s < 5; s++) {
        int i = tid + s*256;
        int r = i / 66, c = i - r*66;
        int gy = by - 1 + r, gx = bx - 1 + c;
        inr[s] = (i < TFILL);
        val[s] = inr[s] && (unsigned)gy < (unsigned)HH && (unsigned)gx < (unsigned)WW;
        soff[s] = r*TCOL + c;
        goff[s] = val[s] ? gy*WW + gx : 0;
    }

    const float* inb = in + (size_t)b*CIN*HW;
    float* sbase = &s_in[0][0][0];

    ull accA[KOC], accB[KOC];
    #pragma unroll
    for (int o = 0; o < KOC; o++) { accA[o] = 0ull; accB[o] = 0ull; }

    #pragma unroll 1
    for (int c0 = 0; c0 < CIN; c0 += CH) {
        __syncthreads();
        #pragma unroll 1
        for (int ci = 0; ci < CH; ci++) {
            const float* cp = inb + (size_t)(c0 + ci)*HW;
            float* sp = sbase + ci*(TROW*TCOL);
            #pragma unroll
            for (int s = 0; s < 5; s++)
                if (inr[s]) sp[soff[s]] = val[s] ? __ldg(cp + goff[s]) : 0.f;
        }
        if (tid < WCNT) {
            int ci = tid / (KOC*9), rem = tid % (KOC*9);
            int o = rem / 9, k = rem % 9;
            float wv = __ldg(w + ((size_t)(oc0 + o)*CIN + c0 + ci)*9 + k);
            s_w[tid] = pack2(wv, wv);
        }
        __syncthreads();

        #pragma unroll 1
        for (int ci = 0; ci < CH; ci++) {
            const ull* wp = s_w + ci*(KOC*9);
            const float* tb = sbase + ci*(TROW*TCOL) + ty*TCOL;
            #pragma unroll
            for (int ky = 0; ky < 3; ky++) {
                const ull* row = (const ull*)(tb + ky*TCOL);
                ull L0 = row[2*tx], L1 = row[2*tx+1], L2 = row[2*tx+2];
                float2 a0 = unpack2(L0), a1 = unpack2(L1), a2 = unpack2(L2);
                ull T1 = pack2(a0.y, a1.x);
                ull T3 = pack2(a1.y, a2.x);
                #pragma unroll
                for (int o = 0; o < KOC; o++) {
                    ull w0 = wp[o*9 + ky*3 + 0];
                    ull w1 = wp[o*9 + ky*3 + 1];
                    ull w2 = wp[o*9 + ky*3 + 2];
                    accA[o] = ffma2(L0, w0, accA[o]);
                    accA[o] = ffma2(T1, w1, accA[o]);
                    accA[o] = ffma2(L1, w2, accA[o]);
                    accB[o] = ffma2(L1, w0, accB[o]);
                    accB[o] = ffma2(T3, w1, accB[o]);
                    accB[o] = ffma2(L2, w2, accB[o]);
                }
            }
        }
    }

    int y = by + ty;
    int x = bx + 4*tx;
    #pragma unroll
    for (int o = 0; o < KOC; o++) {
        float2 vA = unpack2(accA[o]);
        float2 vB = unpack2(accB[o]);
        float bv = bias[oc0 + o];
        vA.x += bv; vA.y += bv; vB.x += bv; vB.y += bv;
        size_t off = ((size_t)(b*COUT + oc0 + o))*HW + y*WW + x;
        float2 r0 = *(const float2*)(addsrc + off);
        float2 r1 = *(const float2*)(addsrc + off + 2);
        vA.x += r0.x; vA.y += r0.y; vB.x += r1.x; vB.y += r1.y;
        *(float2*)(out + off)     = vA;
        *(float2*)(out + off + 2) = vB;
    }
}

// ---------------- launch ----------------
extern "C" void kernel_launch(void* const* d_in, const int* in_sizes, int n_in,
                              void* d_out, int out_size) {
    const float* feature1 = (const float*)d_in[0];
    const float* feature2 = (const float*)d_in[1];
    const float* flow     = (const float*)d_in[2];
    const float* up_w     = (const float*)d_in[3];
    const float* w1 = (const float*)d_in[4];  const float* b1 = (const float*)d_in[5];
    const float* w2 = (const float*)d_in[6];  const float* b2 = (const float*)d_in[7];
    const float* w3 = (const float*)d_in[8];  const float* b3 = (const float*)d_in[9];
    const float* w4 = (const float*)d_in[10]; const float* b4 = (const float*)d_in[11];
    float* out = (float*)d_out;

    float *p_flow_up, *p_f2w, *p_corr, *p_h1, *p_h2, *p_h3;
    cudaGetSymbolAddress((void**)&p_flow_up, g_flow_up);
    cudaGetSymbolAddress((void**)&p_f2w,     g_f2w);
    cudaGetSymbolAddress((void**)&p_corr,    g_corr);
    cudaGetSymbolAddress((void**)&p_h1,      g_h1);
    cudaGetSymbolAddress((void**)&p_h2,      g_h2);
    cudaGetSymbolAddress((void**)&p_h3,      g_h3);

    constexpr int SMEM_CONV = 4*34*132*4 + 4*18*8;   // 72384 B
    cudaFuncSetAttribute(k_conv2<49,128,4>, cudaFuncAttributeMaxDynamicSharedMemorySize, SMEM_CONV);
    cudaFuncSetAttribute(k_conv2<128,64,4>, cudaFuncAttributeMaxDynamicSharedMemorySize, SMEM_CONV);
    cudaFuncSetAttribute(k_conv2<64,32,4>,  cudaFuncAttributeMaxDynamicSharedMemorySize, SMEM_CONV);

    k_upsample<<<(BB*2*HW + 255)/256, 256>>>(flow, up_w, p_flow_up);
    k_warp<<<dim3(HH, BB, 4), 128>>>(feature2, p_flow_up, p_f2w);
    k_corr7<<<dim3(4, 4, BB*7), 128>>>(feature1, p_f2w, p_corr);
    k_conv2<49,128,4><<<dim3(1, 4, BB*64), 256, SMEM_CONV>>>(p_corr, w1, b1, p_h1, 0.1f);
    k_conv2<128,64,4><<<dim3(1, 4, BB*32), 256, SMEM_CONV>>>(p_h1,  w2, b2, p_h2, 0.1f);
    k_conv2<64,32,4><<<dim3(1, 4, BB*16), 256, SMEM_CONV>>>(p_h2,  w3, b3, p_h3, 0.1f);
    k_conv4<<<dim3(2, 8, BB), dim3(16, 16)>>>(p_h3, w4, b4, out, p_flow_up);
}